// round 2
// baseline (speedup 1.0000x reference)
#include <cuda_runtime.h>

// TCLoss: total-correlation style loss over pairwise Gaussian log-densities.
// N=2048 samples, D=64 dims.
//
// For each (i,j,d): x = -0.5*((z_i,d - m_j,d)^2 * exp(-lv_j,d) + lv_j,d + LOG2PI)
// out = mean_i [ sum_d logsumexp_j x  -  logsumexp_j sum_d x ]
//
// Work in log2 domain: y = LOG2E * x = a_jd * z^2 + b_jd * z + g_jd  (2 FMA)
// where per (j,d):  w = -0.5*LOG2E*exp(-lv),  a=w, b=-2*m*w, g=w*m^2 -0.5*LOG2E*(lv+LOG2PI)
//
// Per-dim logsumexp needs no max trick (terms bounded above by ~e^2, best-match
// term is O(1), so fp32 direct sum of 2^y is safe). The scalar S=sum_d y is
// O(-300), so online base-2 LSE (m,s) per (i,j), 1 EX2/pair via ex2(-|S-m|).
//
// Parallelization: warp owns one i, lane owns dims {2l,2l+1}. j is tiled into
// 37 chunks held in smem (shared by 8 warps/block). 2048 i-groups(256) x 37
// chunks = 9472 units = 16 units for each of 592 persistent blocks (perfect
// balance). Partials (64 dim-sums + (m,s)) per (i,chunk) go to global scratch;
// two small deterministic reduction kernels finish.

#define LOG2E   1.44269504088896340736f
#define LN2     0.69314718055994530942f
#define LOG2PI  1.83787706640934548356f

#define NPTS    2048
#define DDIM    64
#define NCHUNK  37
#define WPB     8                    // warps per block (i's per block)
#define NGROUP  (NPTS / WPB)         // 256 i-groups
#define NUNITS  (NGROUP * NCHUNK)    // 9472
#define NBLOCKS 592                  // 148*4 ; 9472/592 == 16 units/block
#define TMAX    56                   // max j's per chunk

// Scratch (static device arrays; no allocation).
__device__ float g_psum[NPTS * NCHUNK * DDIM];  // per-(i,chunk) per-dim sums of 2^y
__device__ float g_pm[NPTS * NCHUNK];           // per-(i,chunk) running max of S (log2)
__device__ float g_ps[NPTS * NCHUNK];           // per-(i,chunk) scaled sum
__device__ float g_val[NPTS];                   // per-i result

static __device__ __forceinline__ float ex2f(float x) {
    float r; asm("ex2.approx.ftz.f32 %0, %1;" : "=f"(r) : "f"(x)); return r;
}
static __device__ __forceinline__ float lg2f(float x) {
    float r; asm("lg2.approx.f32 %0, %1;" : "=f"(r) : "f"(x)); return r;
}
// Warp all-reduce sum via butterfly shuffles (redux.f32 unsupported on sm_100 PTX target)
static __device__ __forceinline__ float warp_sum32(float x) {
    #pragma unroll
    for (int off = 16; off; off >>= 1)
        x += __shfl_xor_sync(0xffffffffu, x, off);
    return x;
}

static __device__ __forceinline__ void coeffs(float mm, float lv,
                                              float& a, float& b, float& g) {
    float iv = ex2f(-LOG2E * lv);          // exp(-lv)
    float w  = -0.5f * LOG2E * iv;
    float t  = w * mm;
    a = w;
    b = -(t + t);                          // -2*m*w
    g = fmaf(t, mm, -0.5f * LOG2E * (lv + LOG2PI));
}

__global__ __launch_bounds__(256, 4)
void tc_main_kernel(const float* __restrict__ z,
                    const float* __restrict__ zmean,
                    const float* __restrict__ zlv)
{
    __shared__ float sA[TMAX * DDIM];
    __shared__ float sB[TMAX * DDIM];
    __shared__ float sG[TMAX * DDIM];

    const int tid  = threadIdx.x;
    const int wid  = tid >> 5;
    const int lane = tid & 31;

    for (int u = blockIdx.x; u < NUNITS; u += NBLOCKS) {
        const int ig  = u & (NGROUP - 1);
        const int c   = u >> 8;                       // 0..36
        const int js  = c * 55 + (c < 13 ? c : 13);   // chunk start
        const int cnt = 55 + (c < 13 ? 1 : 0);        // 55 or 56 j's

        __syncthreads();  // previous unit's readers done before overwrite
        // ---- cooperative tile load + transform (coalesced float4) ----
        {
            const float4* m4p = (const float4*)(zmean + js * DDIM);
            const float4* l4p = (const float4*)(zlv   + js * DDIM);
            const int n4 = (cnt * DDIM) >> 2;
            for (int e = tid; e < n4; e += 256) {
                float4 mv = m4p[e];
                float4 lv = l4p[e];
                float4 av, bv, gv;
                coeffs(mv.x, lv.x, av.x, bv.x, gv.x);
                coeffs(mv.y, lv.y, av.y, bv.y, gv.y);
                coeffs(mv.z, lv.z, av.z, bv.z, gv.z);
                coeffs(mv.w, lv.w, av.w, bv.w, gv.w);
                ((float4*)sA)[e] = av;
                ((float4*)sB)[e] = bv;
                ((float4*)sG)[e] = gv;
            }
        }
        __syncthreads();

        // ---- per-warp: one i, lanes cover 64 dims as float2 ----
        const int i = ig * WPB + wid;
        const float2 zv = ((const float2*)z)[i * 32 + lane];
        const float z0 = zv.x, z1 = zv.y;
        const float zz0 = z0 * z0, zz1 = z1 * z1;
        float acc0 = 0.f, acc1 = 0.f;
        float m = __int_as_float(0xff800000);  // -inf
        float s = 0.f;

        const float2* A2 = (const float2*)sA;
        const float2* B2 = (const float2*)sB;
        const float2* G2 = (const float2*)sG;

        #pragma unroll 2
        for (int j = 0; j < cnt; ++j) {
            const float2 a = A2[j * 32 + lane];
            const float2 b = B2[j * 32 + lane];
            const float2 g = G2[j * 32 + lane];
            const float y0 = fmaf(a.x, zz0, fmaf(b.x, z0, g.x));
            const float y1 = fmaf(a.y, zz1, fmaf(b.y, z1, g.y));
            acc0 += ex2f(y0);
            acc1 += ex2f(y1);
            // scalar online logsumexp (base 2) over S = sum_d y
            const float S = warp_sum32(y0 + y1);
            const float d = S - m;
            const float e = ex2f(-fabsf(d));   // covers both branches
            if (d > 0.f) { s = fmaf(s, e, 1.f); m = S; }
            else         { s += e; }
        }

        ((float2*)g_psum)[(i * NCHUNK + c) * 32 + lane] = make_float2(acc0, acc1);
        if (lane == 0) {
            g_pm[i * NCHUNK + c] = m;
            g_ps[i * NCHUNK + c] = s;
        }
    }
}

// One warp per i: combine 37 chunk partials -> g_val[i]
__global__ __launch_bounds__(256)
void tc_reduce_i()
{
    const int wid  = threadIdx.x >> 5;
    const int lane = threadIdx.x & 31;
    const int i    = blockIdx.x * WPB + wid;

    // per-dim totals then sum_d log2
    float s0 = 0.f, s1 = 0.f;
    const float2* P = (const float2*)g_psum;
    #pragma unroll
    for (int cc = 0; cc < NCHUNK; ++cc) {
        const float2 v = P[(i * NCHUNK + cc) * 32 + lane];
        s0 += v.x; s1 += v.y;
    }
    float t = lg2f(s0) + lg2f(s1);
    #pragma unroll
    for (int off = 16; off; off >>= 1)
        t += __shfl_xor_sync(0xffffffffu, t, off);

    // merge (m,s) pairs across chunks, then across lanes
    float ml = __int_as_float(0xff800000);
    float sl = 0.f;
    for (int cc = lane; cc < NCHUNK; cc += 32) {
        const float mc = g_pm[i * NCHUNK + cc];
        const float sc = g_ps[i * NCHUNK + cc];
        const float M  = fmaxf(ml, mc);
        sl = sl * ex2f(ml - M) + sc * ex2f(mc - M);
        ml = M;
    }
    #pragma unroll
    for (int off = 16; off; off >>= 1) {
        const float mo = __shfl_xor_sync(0xffffffffu, ml, off);
        const float so = __shfl_xor_sync(0xffffffffu, sl, off);
        const float M  = fmaxf(ml, mo);
        sl = sl * ex2f(ml - M) + so * ex2f(mo - M);
        ml = M;
    }

    if (lane == 0)
        g_val[i] = LN2 * (t - (ml + lg2f(sl)));
}

// Deterministic final mean over 2048 values.
__global__ __launch_bounds__(1024)
void tc_final(float* __restrict__ out)
{
    __shared__ float sm[1024];
    const int t = threadIdx.x;
    sm[t] = g_val[t] + g_val[t + 1024];
    __syncthreads();
    #pragma unroll
    for (int off = 512; off; off >>= 1) {
        if (t < off) sm[t] += sm[t + off];
        __syncthreads();
    }
    if (t == 0) out[0] = sm[0] * (1.0f / (float)NPTS);
}

extern "C" void kernel_launch(void* const* d_in, const int* in_sizes, int n_in,
                              void* d_out, int out_size)
{
    const float* z  = (const float*)d_in[0];
    const float* zm = (const float*)d_in[1];
    const float* zl = (const float*)d_in[2];
    tc_main_kernel<<<NBLOCKS, 256>>>(z, zm, zl);
    tc_reduce_i<<<NPTS / WPB, 256>>>();
    tc_final<<<1, 1024>>>((float*)d_out);
}

// round 3
// speedup vs baseline: 1.7695x; 1.7695x over previous
#include <cuda_runtime.h>

// TCLoss, N=2048, D=64.
// y_ijd = LOG2E * log N(z_i,d ; m_j,d, exp(lv_j,d)) = a_jd*z^2 + b_jd*z + g_jd
// out = mean_i [ LN2*( sum_d log2 sum_j 2^y  -  log2sumexp2_j sum_d y ) ]
//
// Pipeline:
//  k0: precompute a,b,g (2048x64 each) into gmem.
//  k1: main. Persistent blocks; unit = (i-group of 16) x (j-chunk of 64).
//      Tile of 64 j-coeffs staged in smem (pure copy). Warp owns 2 i's,
//      lane owns dims {2l,2l+1}. Per batch of 8 j's: 2 FMA + 2 EX2 per
//      pair/i, then a 9-shuffle multi-value butterfly reduces all 8 scalar
//      sums S_j at once; each lane keeps a private online-LSE (m,s) for its
//      j-class, merged across classes (xor 4,8,16) once per chunk.
//  k2: per-i reduction over 32 chunk partials. k3: mean.

#define LOG2E   1.44269504088896340736f
#define LN2     0.69314718055994530942f
#define LOG2PI  1.83787706640934548356f
#define NEG_INF __int_as_float(0xff800000)

#define NPTS    2048
#define DDIM    64
#define TJ      64                   // j's per chunk
#define NCHUNK  (NPTS / TJ)          // 32
#define IPB     16                   // i's per block (8 warps x 2)
#define NGROUP  (NPTS / IPB)         // 128
#define NUNITS  (NGROUP * NCHUNK)    // 4096
#define NBLOCKS 592

// Static scratch (no allocation).
__device__ float g_cA[NPTS * DDIM];
__device__ float g_cB[NPTS * DDIM];
__device__ float g_cG[NPTS * DDIM];
__device__ float g_psum[NPTS * NCHUNK * DDIM];  // per-(i,chunk) per-dim sums of 2^y
__device__ float g_pm[NPTS * NCHUNK];           // per-(i,chunk) LSE max (log2)
__device__ float g_ps[NPTS * NCHUNK];           // per-(i,chunk) LSE scaled sum
__device__ float g_val[NPTS];                   // per-i result

static __device__ __forceinline__ float ex2f(float x) {
    float r; asm("ex2.approx.ftz.f32 %0, %1;" : "=f"(r) : "f"(x)); return r;
}
static __device__ __forceinline__ float lg2f(float x) {
    float r; asm("lg2.approx.f32 %0, %1;" : "=f"(r) : "f"(x)); return r;
}

// Online base-2 logsumexp update with a single EX2.
static __device__ __forceinline__ void lse_up(float& m, float& s, float S) {
    const float d = S - m;
    const float e = ex2f(-fabsf(d));   // ex2(-inf)=0 handles first call (m=-inf)
    if (d > 0.f) { s = fmaf(s, e, 1.f); m = S; }
    else         { s += e; }
}

// Reduce 8 values (t[k], distributed across 32 lanes) in 9 shuffles.
// Returns, on every lane, the full 32-lane sum of t[(lane>>2)&7].
static __device__ __forceinline__ float mred8(float t[8], unsigned lane) {
    #pragma unroll
    for (int k = 0; k < 4; ++k) {
        const float send = (lane & 16) ? t[k] : t[k + 4];
        const float keep = (lane & 16) ? t[k + 4] : t[k];
        t[k] = keep + __shfl_xor_sync(0xffffffffu, send, 16);
    }
    #pragma unroll
    for (int k = 0; k < 2; ++k) {
        const float send = (lane & 8) ? t[k] : t[k + 2];
        const float keep = (lane & 8) ? t[k + 2] : t[k];
        t[k] = keep + __shfl_xor_sync(0xffffffffu, send, 8);
    }
    {
        const float send = (lane & 4) ? t[0] : t[1];
        const float keep = (lane & 4) ? t[1] : t[0];
        t[0] = keep + __shfl_xor_sync(0xffffffffu, send, 4);
    }
    float v = t[0];
    v += __shfl_xor_sync(0xffffffffu, v, 2);
    v += __shfl_xor_sync(0xffffffffu, v, 1);
    return v;
}

// Merge per-lane (m,s) across the 8 j-classes (lane bits 2..4). Lane 0 ends
// with each class counted exactly once (bits 0,1 index replicas -> untouched).
static __device__ __forceinline__ void merge_classes(float& m, float& s) {
    #pragma unroll
    for (int off = 4; off <= 16; off <<= 1) {
        const float mo = __shfl_xor_sync(0xffffffffu, m, off);
        const float so = __shfl_xor_sync(0xffffffffu, s, off);
        const float M  = fmaxf(m, mo);
        s = s * ex2f(m - M) + so * ex2f(mo - M);
        m = M;
    }
}

static __device__ __forceinline__ void coeffs(float mm, float lv,
                                              float& a, float& b, float& g) {
    const float iv = ex2f(-LOG2E * lv);          // exp(-lv)
    const float w  = -0.5f * LOG2E * iv;
    const float t  = w * mm;
    a = w;
    b = -(t + t);
    g = fmaf(t, mm, -0.5f * LOG2E * (lv + LOG2PI));
}

// k0: precompute coefficient arrays (float4 granularity; 32768 float4s).
__global__ __launch_bounds__(256)
void tc_coeff_kernel(const float* __restrict__ zmean, const float* __restrict__ zlv)
{
    const int e = blockIdx.x * 256 + threadIdx.x;
    const float4 mv = ((const float4*)zmean)[e];
    const float4 lv = ((const float4*)zlv)[e];
    float4 av, bv, gv;
    coeffs(mv.x, lv.x, av.x, bv.x, gv.x);
    coeffs(mv.y, lv.y, av.y, bv.y, gv.y);
    coeffs(mv.z, lv.z, av.z, bv.z, gv.z);
    coeffs(mv.w, lv.w, av.w, bv.w, gv.w);
    ((float4*)g_cA)[e] = av;
    ((float4*)g_cB)[e] = bv;
    ((float4*)g_cG)[e] = gv;
}

// k1: main pairwise kernel.
__global__ __launch_bounds__(256, 3)
void tc_main_kernel(const float* __restrict__ z)
{
    __shared__ float shA[TJ * DDIM];
    __shared__ float shB[TJ * DDIM];
    __shared__ float shG[TJ * DDIM];

    const int tid  = threadIdx.x;
    const int wid  = tid >> 5;
    const unsigned lane = tid & 31;

    for (int u = blockIdx.x; u < NUNITS; u += NBLOCKS) {
        const int ig = u & (NGROUP - 1);
        const int c  = u >> 7;
        const int js = c * TJ;

        __syncthreads();  // previous unit's readers done
        {
            const float4* pa = (const float4*)(g_cA + js * DDIM);
            const float4* pb = (const float4*)(g_cB + js * DDIM);
            const float4* pg = (const float4*)(g_cG + js * DDIM);
            #pragma unroll
            for (int e = tid; e < TJ * DDIM / 4; e += 256) {
                ((float4*)shA)[e] = pa[e];
                ((float4*)shB)[e] = pb[e];
                ((float4*)shG)[e] = pg[e];
            }
        }
        __syncthreads();

        const int i0 = ig * IPB + wid * 2;
        const float2 zva = ((const float2*)z)[i0 * 32 + lane];
        const float2 zvb = ((const float2*)z)[(i0 + 1) * 32 + lane];
        const float zA0 = zva.x, zA1 = zva.y, zB0 = zvb.x, zB1 = zvb.y;
        const float qA0 = zA0 * zA0, qA1 = zA1 * zA1;
        const float qB0 = zB0 * zB0, qB1 = zB1 * zB1;

        float aA0 = 0.f, aA1 = 0.f, aB0 = 0.f, aB1 = 0.f;
        float mA = NEG_INF, sA = 0.f, mB = NEG_INF, sB = 0.f;

        const float2* A2 = (const float2*)shA;
        const float2* B2 = (const float2*)shB;
        const float2* G2 = (const float2*)shG;

        #pragma unroll 1
        for (int jb = 0; jb < TJ / 8; ++jb) {
            float tA[8], tB[8];
            #pragma unroll
            for (int k = 0; k < 8; ++k) {
                const int j = jb * 8 + k;
                const float2 a = A2[j * 32 + lane];
                const float2 b = B2[j * 32 + lane];
                const float2 g = G2[j * 32 + lane];
                const float yA0 = fmaf(a.x, qA0, fmaf(b.x, zA0, g.x));
                const float yA1 = fmaf(a.y, qA1, fmaf(b.y, zA1, g.y));
                const float yB0 = fmaf(a.x, qB0, fmaf(b.x, zB0, g.x));
                const float yB1 = fmaf(a.y, qB1, fmaf(b.y, zB1, g.y));
                aA0 += ex2f(yA0);
                aA1 += ex2f(yA1);
                aB0 += ex2f(yB0);
                aB1 += ex2f(yB1);
                tA[k] = yA0 + yA1;
                tB[k] = yB0 + yB1;
            }
            lse_up(mA, sA, mred8(tA, lane));
            lse_up(mB, sB, mred8(tB, lane));
        }

        ((float2*)g_psum)[(i0 * NCHUNK + c) * 32 + lane]       = make_float2(aA0, aA1);
        ((float2*)g_psum)[((i0 + 1) * NCHUNK + c) * 32 + lane] = make_float2(aB0, aB1);
        merge_classes(mA, sA);
        merge_classes(mB, sB);
        if (lane == 0) {
            g_pm[i0 * NCHUNK + c] = mA;
            g_ps[i0 * NCHUNK + c] = sA;
            g_pm[(i0 + 1) * NCHUNK + c] = mB;
            g_ps[(i0 + 1) * NCHUNK + c] = sB;
        }
    }
}

// k2: one warp per i combines the 32 chunk partials.
__global__ __launch_bounds__(256)
void tc_reduce_i()
{
    const int wid  = threadIdx.x >> 5;
    const int lane = threadIdx.x & 31;
    const int i    = blockIdx.x * 8 + wid;

    float s0 = 0.f, s1 = 0.f;
    const float2* P = (const float2*)g_psum;
    #pragma unroll
    for (int cc = 0; cc < NCHUNK; ++cc) {
        const float2 v = P[(i * NCHUNK + cc) * 32 + lane];
        s0 += v.x; s1 += v.y;
    }
    float t = lg2f(s0) + lg2f(s1);
    #pragma unroll
    for (int off = 16; off; off >>= 1)
        t += __shfl_xor_sync(0xffffffffu, t, off);

    float ml = g_pm[i * NCHUNK + lane];   // NCHUNK==32: one chunk per lane
    float sl = g_ps[i * NCHUNK + lane];
    #pragma unroll
    for (int off = 16; off; off >>= 1) {
        const float mo = __shfl_xor_sync(0xffffffffu, ml, off);
        const float so = __shfl_xor_sync(0xffffffffu, sl, off);
        const float M  = fmaxf(ml, mo);
        sl = sl * ex2f(ml - M) + so * ex2f(mo - M);
        ml = M;
    }

    if (lane == 0)
        g_val[i] = LN2 * (t - (ml + lg2f(sl)));
}

// k3: deterministic final mean over 2048 values.
__global__ __launch_bounds__(1024)
void tc_final(float* __restrict__ out)
{
    __shared__ float sm[1024];
    const int t = threadIdx.x;
    sm[t] = g_val[t] + g_val[t + 1024];
    __syncthreads();
    #pragma unroll
    for (int off = 512; off; off >>= 1) {
        if (t < off) sm[t] += sm[t + off];
        __syncthreads();
    }
    if (t == 0) out[0] = sm[0] * (1.0f / (float)NPTS);
}

extern "C" void kernel_launch(void* const* d_in, const int* in_sizes, int n_in,
                              void* d_out, int out_size)
{
    const float* z  = (const float*)d_in[0];
    const float* zm = (const float*)d_in[1];
    const float* zl = (const float*)d_in[2];
    tc_coeff_kernel<<<NPTS * DDIM / 1024, 256>>>(zm, zl);
    tc_main_kernel<<<NBLOCKS, 256>>>(z);
    tc_reduce_i<<<NPTS / 8, 256>>>();
    tc_final<<<1, 1024>>>((float*)d_out);
}

// round 4
// speedup vs baseline: 1.8425x; 1.0413x over previous
#include <cuda_runtime.h>

// TCLoss, N=2048, D=64.
// y_ijd = LOG2E * log N(z_i,d ; m_j,d, exp(lv_j,d)) = a_jd*z^2 + b_jd*z + g_jd
// out = mean_i [ LN2*( sum_d log2 sum_j 2^y  -  log2sumexp2_j sum_d y ) ]
//
// k0: precompute coeffs, packed: AB as float4 (a0,a1,b0,b1) per (j,dim-pair),
//     G as float2 -> 2 LDS per j in the hot loop.
// k1: persistent main. Unit = (16 i's) x (64 j's tile in smem). Warp owns 2
//     i's, lane owns dims {2l,2l+1}. Batches of 8 j's; the 9-shuffle
//     multi-value butterfly + online-LSE of batch k-1 is interleaved with the
//     FMA/EX2 compute of batch k (software pipeline) so MUFU never idles.
// k2: per-i reduction over 32 chunk partials. k3: mean.

#define LOG2E   1.44269504088896340736f
#define LN2     0.69314718055994530942f
#define LOG2PI  1.83787706640934548356f
#define NEG_INF __int_as_float(0xff800000)

#define NPTS    2048
#define DDIM    64
#define TJ      64                   // j's per chunk
#define NCHUNK  (NPTS / TJ)          // 32
#define IPB     16                   // i's per block (8 warps x 2)
#define NGROUP  (NPTS / IPB)         // 128
#define NUNITS  (NGROUP * NCHUNK)    // 4096
#define NBLOCKS 296                  // 148 SMs x 2 resident blocks

// Static scratch (no allocation).
__device__ float4 g_cAB[NPTS * DDIM / 2];       // (a0,a1,b0,b1) per (j, dim-pair)
__device__ float2 g_cG[NPTS * DDIM / 2];        // (g0,g1) per (j, dim-pair)
__device__ float g_psum[NPTS * NCHUNK * DDIM];  // per-(i,chunk) per-dim sums of 2^y
__device__ float g_pm[NPTS * NCHUNK];           // per-(i,chunk) LSE max (log2)
__device__ float g_ps[NPTS * NCHUNK];           // per-(i,chunk) LSE scaled sum
__device__ float g_val[NPTS];                   // per-i result

static __device__ __forceinline__ float ex2f(float x) {
    float r; asm("ex2.approx.ftz.f32 %0, %1;" : "=f"(r) : "f"(x)); return r;
}
static __device__ __forceinline__ float lg2f(float x) {
    float r; asm("lg2.approx.f32 %0, %1;" : "=f"(r) : "f"(x)); return r;
}

// Online base-2 logsumexp update with a single EX2.
static __device__ __forceinline__ void lse_up(float& m, float& s, float S) {
    const float d = S - m;
    const float e = ex2f(-fabsf(d));   // ex2(-inf)=0 handles first call (m=-inf)
    if (d > 0.f) { s = fmaf(s, e, 1.f); m = S; }
    else         { s += e; }
}

// Reduce 8 values (t[k], distributed across 32 lanes) in 9 shuffles.
// Returns, on every lane, the full 32-lane sum of t[(lane>>2)&7].
static __device__ __forceinline__ float mred8(float t[8], unsigned lane) {
    #pragma unroll
    for (int k = 0; k < 4; ++k) {
        const float send = (lane & 16) ? t[k] : t[k + 4];
        const float keep = (lane & 16) ? t[k + 4] : t[k];
        t[k] = keep + __shfl_xor_sync(0xffffffffu, send, 16);
    }
    #pragma unroll
    for (int k = 0; k < 2; ++k) {
        const float send = (lane & 8) ? t[k] : t[k + 2];
        const float keep = (lane & 8) ? t[k + 2] : t[k];
        t[k] = keep + __shfl_xor_sync(0xffffffffu, send, 8);
    }
    {
        const float send = (lane & 4) ? t[0] : t[1];
        const float keep = (lane & 4) ? t[1] : t[0];
        t[0] = keep + __shfl_xor_sync(0xffffffffu, send, 4);
    }
    float v = t[0];
    v += __shfl_xor_sync(0xffffffffu, v, 2);
    v += __shfl_xor_sync(0xffffffffu, v, 1);
    return v;
}

// Merge per-lane (m,s) across the 8 j-classes (lane bits 2..4).
static __device__ __forceinline__ void merge_classes(float& m, float& s) {
    #pragma unroll
    for (int off = 4; off <= 16; off <<= 1) {
        const float mo = __shfl_xor_sync(0xffffffffu, m, off);
        const float so = __shfl_xor_sync(0xffffffffu, s, off);
        const float M  = fmaxf(m, mo);
        s = s * ex2f(m - M) + so * ex2f(mo - M);
        m = M;
    }
}

static __device__ __forceinline__ void coeffs(float mm, float lv,
                                              float& a, float& b, float& g) {
    const float iv = ex2f(-LOG2E * lv);          // exp(-lv)
    const float w  = -0.5f * LOG2E * iv;
    const float t  = w * mm;
    a = w;
    b = -(t + t);
    g = fmaf(t, mm, -0.5f * LOG2E * (lv + LOG2PI));
}

// k0: precompute packed coefficient arrays. One thread per input float4
// (dims 4f..4f+3 of row j), writing 2 AB float4s and 1 G float4.
__global__ __launch_bounds__(256)
void tc_coeff_kernel(const float* __restrict__ zmean, const float* __restrict__ zlv)
{
    const int e = blockIdx.x * 256 + threadIdx.x;   // [0, 32768)
    const int j = e >> 4;
    const int f = e & 15;                           // float4 index within row
    const float4 mv = ((const float4*)zmean)[e];
    const float4 lv = ((const float4*)zlv)[e];
    float a0, b0, g0, a1, b1, g1, a2, b2, g2, a3, b3, g3;
    coeffs(mv.x, lv.x, a0, b0, g0);
    coeffs(mv.y, lv.y, a1, b1, g1);
    coeffs(mv.z, lv.z, a2, b2, g2);
    coeffs(mv.w, lv.w, a3, b3, g3);
    g_cAB[(j << 5) + 2 * f]     = make_float4(a0, a1, b0, b1);
    g_cAB[(j << 5) + 2 * f + 1] = make_float4(a2, a3, b2, b3);
    g_cG[(j << 5) + 2 * f]      = make_float2(g0, g1);
    g_cG[(j << 5) + 2 * f + 1]  = make_float2(g2, g3);
}

// k1: main pairwise kernel.
__global__ __launch_bounds__(256, 2)
void tc_main_kernel(const float* __restrict__ z)
{
    __shared__ float4 shAB[TJ * 32];   // 32 KB
    __shared__ float2 shG[TJ * 32];    // 16 KB

    const int tid  = threadIdx.x;
    const int wid  = tid >> 5;
    const unsigned lane = tid & 31;

    for (int u = blockIdx.x; u < NUNITS; u += NBLOCKS) {
        const int ig = u & (NGROUP - 1);
        const int c  = u >> 7;
        const int js = c * TJ;

        __syncthreads();  // previous unit's readers done
        {
            const float4* pab = g_cAB + js * 32;
            const float4* pg  = (const float4*)(g_cG + js * 32);
            #pragma unroll
            for (int e = tid; e < TJ * 32; e += 256)
                shAB[e] = pab[e];
            #pragma unroll
            for (int e = tid; e < TJ * 16; e += 256)
                ((float4*)shG)[e] = pg[e];
        }
        __syncthreads();

        const int i0 = ig * IPB + wid * 2;
        const float2 zva = ((const float2*)z)[i0 * 32 + lane];
        const float2 zvb = ((const float2*)z)[(i0 + 1) * 32 + lane];
        const float zA0 = zva.x, zA1 = zva.y, zB0 = zvb.x, zB1 = zvb.y;
        const float qA0 = zA0 * zA0, qA1 = zA1 * zA1;
        const float qB0 = zB0 * zB0, qB1 = zB1 * zB1;

        float aA0 = 0.f, aA1 = 0.f, aB0 = 0.f, aB1 = 0.f;
        float mA = NEG_INF, sA = 0.f, mB = NEG_INF, sB = 0.f;

        float tPA[8], tPB[8];   // previous batch's scalar partials

        // Software pipeline: compute batch jb, then reduce batch jb-1.
        #pragma unroll
        for (int jb = 0; jb < TJ / 8; ++jb) {
            float tCA[8], tCB[8];
            #pragma unroll
            for (int k = 0; k < 8; ++k) {
                const int j = jb * 8 + k;
                const float4 ab = shAB[j * 32 + lane];
                const float2 g  = shG[j * 32 + lane];
                const float yA0 = fmaf(ab.x, qA0, fmaf(ab.z, zA0, g.x));
                const float yA1 = fmaf(ab.y, qA1, fmaf(ab.w, zA1, g.y));
                const float yB0 = fmaf(ab.x, qB0, fmaf(ab.z, zB0, g.x));
                const float yB1 = fmaf(ab.y, qB1, fmaf(ab.w, zB1, g.y));
                aA0 += ex2f(yA0);
                aA1 += ex2f(yA1);
                aB0 += ex2f(yB0);
                aB1 += ex2f(yB1);
                tCA[k] = yA0 + yA1;
                tCB[k] = yB0 + yB1;
            }
            if (jb > 0) {
                lse_up(mA, sA, mred8(tPA, lane));
                lse_up(mB, sB, mred8(tPB, lane));
            }
            #pragma unroll
            for (int k = 0; k < 8; ++k) { tPA[k] = tCA[k]; tPB[k] = tCB[k]; }
        }
        lse_up(mA, sA, mred8(tPA, lane));
        lse_up(mB, sB, mred8(tPB, lane));

        ((float2*)g_psum)[(i0 * NCHUNK + c) * 32 + lane]       = make_float2(aA0, aA1);
        ((float2*)g_psum)[((i0 + 1) * NCHUNK + c) * 32 + lane] = make_float2(aB0, aB1);
        merge_classes(mA, sA);
        merge_classes(mB, sB);
        if (lane == 0) {
            g_pm[i0 * NCHUNK + c] = mA;
            g_ps[i0 * NCHUNK + c] = sA;
            g_pm[(i0 + 1) * NCHUNK + c] = mB;
            g_ps[(i0 + 1) * NCHUNK + c] = sB;
        }
    }
}

// k2: one warp per i combines the 32 chunk partials.
__global__ __launch_bounds__(256)
void tc_reduce_i()
{
    const int wid  = threadIdx.x >> 5;
    const int lane = threadIdx.x & 31;
    const int i    = blockIdx.x * 8 + wid;

    float s0 = 0.f, s1 = 0.f;
    const float2* P = (const float2*)g_psum;
    #pragma unroll
    for (int cc = 0; cc < NCHUNK; ++cc) {
        const float2 v = P[(i * NCHUNK + cc) * 32 + lane];
        s0 += v.x; s1 += v.y;
    }
    float t = lg2f(s0) + lg2f(s1);
    #pragma unroll
    for (int off = 16; off; off >>= 1)
        t += __shfl_xor_sync(0xffffffffu, t, off);

    float ml = g_pm[i * NCHUNK + lane];   // NCHUNK==32: one chunk per lane
    float sl = g_ps[i * NCHUNK + lane];
    #pragma unroll
    for (int off = 16; off; off >>= 1) {
        const float mo = __shfl_xor_sync(0xffffffffu, ml, off);
        const float so = __shfl_xor_sync(0xffffffffu, sl, off);
        const float M  = fmaxf(ml, mo);
        sl = sl * ex2f(ml - M) + so * ex2f(mo - M);
        ml = M;
    }

    if (lane == 0)
        g_val[i] = LN2 * (t - (ml + lg2f(sl)));
}

// k3: deterministic final mean (256 threads, shuffle-based).
__global__ __launch_bounds__(256)
void tc_final(float* __restrict__ out)
{
    __shared__ float sm[8];
    const int t = threadIdx.x;
    float v = 0.f;
    #pragma unroll
    for (int k = 0; k < 8; ++k)
        v += g_val[t + k * 256];
    #pragma unroll
    for (int off = 16; off; off >>= 1)
        v += __shfl_xor_sync(0xffffffffu, v, off);
    if ((t & 31) == 0) sm[t >> 5] = v;
    __syncthreads();
    if (t == 0) {
        float r = 0.f;
        #pragma unroll
        for (int k = 0; k < 8; ++k) r += sm[k];
        out[0] = r * (1.0f / (float)NPTS);
    }
}

extern "C" void kernel_launch(void* const* d_in, const int* in_sizes, int n_in,
                              void* d_out, int out_size)
{
    const float* z  = (const float*)d_in[0];
    const float* zm = (const float*)d_in[1];
    const float* zl = (const float*)d_in[2];
    tc_coeff_kernel<<<NPTS * DDIM / 1024, 256>>>(zm, zl);
    tc_main_kernel<<<NBLOCKS, 256>>>(z);
    tc_reduce_i<<<NPTS / 8, 256>>>();
    tc_final<<<1, 256>>>((float*)d_out);
}